// round 6
// baseline (speedup 1.0000x reference)
#include <cuda_runtime.h>

// ExtractLearnableSlices — head-per-block over 16 batches, double-buffered
// software pipeline.
//   x: (B=64, C=64, L=16384) f32
//   channel_params/offset_params: (128,) f32
//   out: (B=64, N=128, W=512) f32
//
// Block (i, g): head i, batches b = 16g .. 16g+15. Params computed once.
// Loop over batches: stage fused channel lerp v[l] = xf[l]+wc*(xc[l]-xf[l])
// (520-float window) into alternating smem buffers; prefetch batch b+2's
// window loads right after the sync; epilogue = 4 outputs/thread time lerp.
// pos = t0 + j in f32, floor via positive int cast — identical to prior rounds.

#define B_DIM   64
#define C_DIM   64
#define L_DIM   16384
#define N_HEADS 128
#define WIDTH   512

#define THREADS 128
#define NB      16                  // batches per block
#define NGROUPS (B_DIM / NB)        // 4
#define SMEM_FLOATS 520             // 130 float4 window

__global__ __launch_bounds__(THREADS) void extract_slices_kernel(
    const float* __restrict__ x,
    const float* __restrict__ channel_params,
    const float* __restrict__ offset_params,
    float* __restrict__ out)
{
    __shared__ float vbuf[2][SMEM_FLOATS];

    const int tid = threadIdx.x;        // 0..127
    const int i   = blockIdx.x;         // head 0..127
    const int b0  = blockIdx.y * NB;    // first batch of group

    // ---- per-head params, once per 8192 outputs (exact same math as before) ----
    const float cp = __ldg(&channel_params[i]);
    const float op = __ldg(&offset_params[i]);

    const float sc      = 1.0f / (1.0f + expf(-cp));
    const float desired = sc * (float)(C_DIM - 1);   // > 0
    const int   fc      = (int)desired;              // floor (positive)
    const int   cc      = min(fc + 1, C_DIM - 1);
    const float wc      = desired - (float)fc;

    const float so  = 1.0f / (1.0f + expf(-op));
    const float t0  = so * (float)(L_DIM - WIDTH);   // > 0
    const int   pf0 = (int)t0;                       // floor (positive)
    const int   l0  = (pf0 - 1) & ~3;                // float4-aligned, slack below

    const int xfo = fc * L_DIM + l0;                 // element offsets, batch-invariant
    const int xco = cc * L_DIM + l0;

    const bool tail = (tid < 2);

    // Prefetch register slots (2-deep pipeline)
    float4 pa[2], pc[2];        // main 128 float4
    float4 pat[2], pct[2];      // 2-float4 tail (tid < 2 only)

    auto LOAD = [&](int bi, int slot) {
        const size_t bb = (size_t)(b0 + bi) * (size_t)(C_DIM * L_DIM);
        const float4* __restrict__ f4 = (const float4*)(x + bb + xfo);
        const float4* __restrict__ c4 = (const float4*)(x + bb + xco);
        pa[slot] = f4[tid];
        pc[slot] = c4[tid];
        if (tail) { pat[slot] = f4[THREADS + tid]; pct[slot] = c4[THREADS + tid]; }
    };

    LOAD(0, 0);
    LOAD(1, 1);

    #pragma unroll
    for (int bi = 0; bi < NB; ++bi) {
        const int slot = bi & 1;
        float* __restrict__ vb = vbuf[slot];
        float4* __restrict__ v4 = (float4*)vb;

        // ---- stage from prefetched regs ----
        {
            const float4 a = pa[slot], c = pc[slot];
            float4 r;
            r.x = a.x + wc * (c.x - a.x);
            r.y = a.y + wc * (c.y - a.y);
            r.z = a.z + wc * (c.z - a.z);
            r.w = a.w + wc * (c.w - a.w);
            v4[tid] = r;
        }
        if (tail) {
            const float4 a = pat[slot], c = pct[slot];
            float4 r;
            r.x = a.x + wc * (c.x - a.x);
            r.y = a.y + wc * (c.y - a.y);
            r.z = a.z + wc * (c.z - a.z);
            r.w = a.w + wc * (c.w - a.w);
            v4[THREADS + tid] = r;
        }
        __syncthreads();   // one sync per iter; double buffer makes this sufficient

        // ---- prefetch batch bi+2 (regs in this slot are now consumed) ----
        if (bi + 2 < NB) LOAD(bi + 2, slot);

        // ---- epilogue: 4 outputs/thread, coalesced STG, conflict-free LDS ----
        float* __restrict__ orow =
            out + ((size_t)(b0 + bi) * N_HEADS + i) * WIDTH + tid;

        #pragma unroll
        for (int k = 0; k < 4; ++k) {
            const float pos = t0 + (float)(tid + k * THREADS);  // exact ref f32 math
            const int   pf  = (int)pos;                         // floor (positive)
            const float wt  = pos - (float)pf;
            const int   idx = pf - l0;                          // in [0, 517]
            const float v0  = vb[idx];
            const float v1  = vb[idx + 1];
            orow[k * THREADS] = v0 + wt * (v1 - v0);
        }
    }
}

extern "C" void kernel_launch(void* const* d_in, const int* in_sizes, int n_in,
                              void* d_out, int out_size)
{
    const float* x  = (const float*)d_in[0];
    const float* ch = (const float*)d_in[1];
    const float* of = (const float*)d_in[2];
    float* out = (float*)d_out;

    dim3 grid(N_HEADS, NGROUPS);
    extract_slices_kernel<<<grid, THREADS>>>(x, ch, of, out);
}